// round 4
// baseline (speedup 1.0000x reference)
#include <cuda_runtime.h>
#include <cuda_bf16.h>
#include <cstdint>

// Problem constants
#define T_LEN 2048
#define BATCH 2
#define EMBED 1024
#define NHEAD 16
#define HDIM  64
#define BHEAD (BATCH * NHEAD)          // 32
#define NTOK  (T_LEN * BATCH)          // 4096
// 0.125 (=64^-0.5) * log2(e): softmax computed in base-2 domain
#define QSCALE 0.18033688011112042f

// Scratch (allocation-free rule: __device__ globals).
// q/k/v are stored as pre-converted tf32 bit patterns; v is transposed [bh][d][t].
__device__ __align__(16) uint32_t g_qb[BHEAD * T_LEN * HDIM];  // [bh][t][d] (pre-scaled)
__device__ __align__(16) uint32_t g_kb[BHEAD * T_LEN * HDIM];  // [bh][t][d]
__device__ __align__(16) uint32_t g_vb[BHEAD * T_LEN * HDIM];  // [bh][d][t]
__device__ __align__(16) float    g_ctx[NTOK * EMBED];         // [t*2+b][e]

// ---------------------------------------------------------------------------
// PTX helpers
// ---------------------------------------------------------------------------
__device__ __forceinline__ uint32_t s2u(const void* p) {
    return (uint32_t)__cvta_generic_to_shared(p);
}
__device__ __forceinline__ uint32_t f2tf(float x) {
    uint32_t r; asm("cvt.rna.tf32.f32 %0, %1;" : "=r"(r) : "f"(x)); return r;
}
__device__ __forceinline__ float ex2f(float x) {
    float r; asm("ex2.approx.f32 %0, %1;" : "=f"(r) : "f"(x)); return r;
}
__device__ __forceinline__ void ldsm4(uint32_t& r0, uint32_t& r1, uint32_t& r2,
                                      uint32_t& r3, uint32_t addr) {
    asm volatile("ldmatrix.sync.aligned.m8n8.x4.shared.b16 {%0,%1,%2,%3}, [%4];"
                 : "=r"(r0), "=r"(r1), "=r"(r2), "=r"(r3) : "r"(addr));
}
__device__ __forceinline__ void mma8(float* c, const uint32_t* a, const uint32_t* b) {
    asm volatile(
        "mma.sync.aligned.m16n8k8.row.col.f32.tf32.tf32.f32 "
        "{%0,%1,%2,%3}, {%4,%5,%6,%7}, {%8,%9}, {%0,%1,%2,%3};\n"
        : "+f"(c[0]), "+f"(c[1]), "+f"(c[2]), "+f"(c[3])
        : "r"(a[0]), "r"(a[1]), "r"(a[2]), "r"(a[3]), "r"(b[0]), "r"(b[1]));
}
__device__ __forceinline__ void cpasync16(uint32_t dst, const void* src) {
    asm volatile("cp.async.cg.shared.global [%0], [%1], 16;" :: "r"(dst), "l"(src));
}
#define CP_COMMIT() asm volatile("cp.async.commit_group;")

// ---------------------------------------------------------------------------
// Kernel 1: QKV projection (tf32 tensor core).
// Block 128x128, BK=32, 256 threads = 8 warps (2 CTAs/SM), warp tile 64x32.
// Epilogue: bias, q pre-scale, rna->tf32 bit conversion, v transpose.
// ---------------------------------------------------------------------------
#define GST 36

__global__ __launch_bounds__(256, 2) void qkv_kernel(
    const float* __restrict__ x,      // [4096,1024]
    const float* __restrict__ w,      // [3072,1024]
    const float* __restrict__ bias)   // [3072]
{
    __shared__ __align__(16) uint32_t As[128 * GST];
    __shared__ __align__(16) uint32_t Bs[128 * GST];

    const int bm = blockIdx.y * 128, bn = blockIdx.x * 128;
    const int tid = threadIdx.x, wid = tid >> 5, lane = tid & 31;
    const int gr = lane >> 2, tig = lane & 3;
    const int wm = (wid & 1) * 64, wn = (wid >> 1) * 32;
    const int r0 = tid >> 3, q = tid & 7;

    float acc[4][4][4];
    #pragma unroll
    for (int i = 0; i < 4; i++)
        #pragma unroll
        for (int j = 0; j < 4; j++)
            #pragma unroll
            for (int r = 0; r < 4; r++) acc[i][j][r] = 0.f;

    const float* ap = x + (size_t)(bm + r0) * EMBED + q * 4;
    const float* bp = w + (size_t)(bn + r0) * EMBED + q * 4;

    float4 pa[4], pb[4];
    #pragma unroll
    for (int it = 0; it < 4; it++) {
        pa[it] = *(const float4*)(ap + (size_t)it * 32 * EMBED);
        pb[it] = *(const float4*)(bp + (size_t)it * 32 * EMBED);
    }
    #pragma unroll
    for (int it = 0; it < 4; it++) {
        *(uint4*)(As + (r0 + 32 * it) * GST + q * 4) =
            make_uint4(f2tf(pa[it].x), f2tf(pa[it].y), f2tf(pa[it].z), f2tf(pa[it].w));
        *(uint4*)(Bs + (r0 + 32 * it) * GST + q * 4) =
            make_uint4(f2tf(pb[it].x), f2tf(pb[it].y), f2tf(pb[it].z), f2tf(pb[it].w));
    }
    __syncthreads();

    const uint32_t as_base = s2u(As), bs_base = s2u(Bs);

    #pragma unroll 1
    for (int kb = 0; kb < 32; kb++) {
        if (kb < 31) {
            int k0 = (kb + 1) * 32;
            #pragma unroll
            for (int it = 0; it < 4; it++) {
                pa[it] = *(const float4*)(ap + (size_t)it * 32 * EMBED + k0);
                pb[it] = *(const float4*)(bp + (size_t)it * 32 * EMBED + k0);
            }
        }
        #pragma unroll
        for (int ks = 0; ks < 4; ks++) {
            int k8 = ks * 8;
            uint32_t bfr[4][2];
            #pragma unroll
            for (int p = 0; p < 2; p++) {
                int row = wn + 16 * p + (lane & 7) + ((lane >> 4) << 3);
                int col = k8 + 4 * ((lane >> 3) & 1);
                ldsm4(bfr[2 * p][0], bfr[2 * p][1], bfr[2 * p + 1][0], bfr[2 * p + 1][1],
                      bs_base + (row * GST + col) * 4);
            }
            #pragma unroll
            for (int mi = 0; mi < 4; mi++) {
                uint32_t a[4];
                int row = wm + 16 * mi + (lane & 15);
                int col = k8 + 4 * (lane >> 4);
                ldsm4(a[0], a[1], a[2], a[3], as_base + (row * GST + col) * 4);
                #pragma unroll
                for (int nj = 0; nj < 4; nj++) mma8(acc[mi][nj], a, bfr[nj]);
            }
        }
        __syncthreads();
        if (kb < 31) {
            #pragma unroll
            for (int it = 0; it < 4; it++) {
                *(uint4*)(As + (r0 + 32 * it) * GST + q * 4) =
                    make_uint4(f2tf(pa[it].x), f2tf(pa[it].y), f2tf(pa[it].z), f2tf(pa[it].w));
                *(uint4*)(Bs + (r0 + 32 * it) * GST + q * 4) =
                    make_uint4(f2tf(pb[it].x), f2tf(pb[it].y), f2tf(pb[it].z), f2tf(pb[it].w));
            }
            __syncthreads();
        }
    }

    // Epilogue: bias, q-scaling, tf32 conversion, scatter (v transposed)
    #pragma unroll
    for (int mi = 0; mi < 4; mi++)
        #pragma unroll
        for (int nj = 0; nj < 4; nj++)
            #pragma unroll
            for (int rr = 0; rr < 2; rr++) {
                int m = bm + wm + mi * 16 + gr + 8 * rr;
                int f = bn + wn + nj * 8 + 2 * tig;
                float c0 = acc[mi][nj][rr * 2 + 0] + bias[f];
                float c1 = acc[mi][nj][rr * 2 + 1] + bias[f + 1];
                int which = f >> 10, hd = f & 1023, h = hd >> 6, d = hd & 63;
                int t = m >> 1, bb = m & 1;
                int bh = bb * NHEAD + h;
                if (which == 0) {
                    *(uint2*)(g_qb + ((size_t)bh * T_LEN + t) * HDIM + d) =
                        make_uint2(f2tf(c0 * QSCALE), f2tf(c1 * QSCALE));
                } else if (which == 1) {
                    *(uint2*)(g_kb + ((size_t)bh * T_LEN + t) * HDIM + d) =
                        make_uint2(f2tf(c0), f2tf(c1));
                } else {
                    g_vb[((size_t)bh * HDIM + d) * T_LEN + t] = f2tf(c0);
                    g_vb[((size_t)bh * HDIM + d + 1) * T_LEN + t] = f2tf(c1);
                }
            }
}

// ---------------------------------------------------------------------------
// Kernel 2: flash attention (tf32 tensor core), cp.async double-buffered.
// Block = (bh, 128-query tile), 256 threads = 8 warps; warp owns 16 q-rows.
// Smem (tf32 bits): Qs[128][68], Ps[128][68], 2 stages of (Ks[64][68]+Vs[64][68]).
// All scratch pre-converted/pre-transposed -> tile loads are pure cp.async.
// ---------------------------------------------------------------------------
#define AST 68
#define ATTN_SMEM ((128 + 128 + 4 * 64) * AST * 4)

__global__ __launch_bounds__(256) void attn_kernel()
{
    extern __shared__ uint32_t sm[];
    uint32_t* Qs = sm;                    // [128][68]
    uint32_t* Ps = Qs + 128 * AST;        // [128][68]
    uint32_t* KV = Ps + 128 * AST;        // [K0,V0,K1,V1] each [64][68]

    const int bh = blockIdx.y;
    const int q0 = blockIdx.x * 128;
    const int tid = threadIdx.x, wid = tid >> 5, lane = tid & 31;
    const int gr = lane >> 2, tig = lane & 3;
    const int warp_q = wid * 16;

    const uint32_t* qg = g_qb + (size_t)bh * T_LEN * HDIM;
    const uint32_t* kg = g_kb + (size_t)bh * T_LEN * HDIM;
    const uint32_t* vg = g_vb + (size_t)bh * T_LEN * HDIM;  // [d][t]

    // Q tile via cp.async (part of group 0)
    {
        int r0 = tid >> 4, c4 = (tid & 15) * 4;
        #pragma unroll
        for (int i = 0; i < 8; i++) {
            int r = r0 + 16 * i;
            cpasync16(s2u(Qs + r * AST + c4), qg + (size_t)(q0 + r) * HDIM + c4);
        }
    }
    // K/V tile issue helper (inlined below twice)
    // stage s: K = KV + s*2*64*AST, V = K + 64*AST
    {   // preload tile 0 into stage 0
        #pragma unroll
        for (int j = 0; j < 4; j++) {
            int id = tid + 256 * j;
            int row = id >> 4, c4 = (id & 15) * 4;
            cpasync16(s2u(KV + row * AST + c4), kg + (size_t)row * HDIM + c4);
            cpasync16(s2u(KV + (64 + row) * AST + c4), vg + (size_t)row * T_LEN + 0 + c4);
        }
    }
    CP_COMMIT();

    float accO[8][4];
    #pragma unroll
    for (int nf = 0; nf < 8; nf++)
        #pragma unroll
        for (int r = 0; r < 4; r++) accO[nf][r] = 0.f;
    float m_s[2] = {-1e30f, -1e30f};
    float l_s[2] = {0.f, 0.f};

    const uint32_t qs_base = s2u(Qs), ps_base = s2u(Ps);

    #pragma unroll 1
    for (int it = 0; it < T_LEN / 64; it++) {
        int cur = it & 1;
        if (it < T_LEN / 64 - 1) {
            int nxt = 1 - cur;
            int s0 = (it + 1) * 64;
            uint32_t* Kn = KV + nxt * 2 * 64 * AST;
            #pragma unroll
            for (int j = 0; j < 4; j++) {
                int id = tid + 256 * j;
                int row = id >> 4, c4 = (id & 15) * 4;
                cpasync16(s2u(Kn + row * AST + c4), kg + (size_t)(s0 + row) * HDIM + c4);
                cpasync16(s2u(Kn + (64 + row) * AST + c4),
                          vg + (size_t)row * T_LEN + s0 + c4);
            }
            CP_COMMIT();
            asm volatile("cp.async.wait_group 1;");
        } else {
            asm volatile("cp.async.wait_group 0;");
        }
        __syncthreads();

        const uint32_t ks_base = s2u(KV + cur * 2 * 64 * AST);
        const uint32_t vs_base = ks_base + 64 * AST * 4;

        // S = Q K^T  (warp: 16 q-rows x 64 keys)
        float sfr[8][4];
        #pragma unroll
        for (int nf = 0; nf < 8; nf++)
            #pragma unroll
            for (int r = 0; r < 4; r++) sfr[nf][r] = 0.f;

        #pragma unroll
        for (int ks = 0; ks < 8; ks++) {
            int k8 = ks * 8;
            uint32_t kb[8][2];
            #pragma unroll
            for (int p = 0; p < 4; p++) {
                int row = 16 * p + (lane & 7) + ((lane >> 4) << 3);
                int col = k8 + 4 * ((lane >> 3) & 1);
                ldsm4(kb[2 * p][0], kb[2 * p][1], kb[2 * p + 1][0], kb[2 * p + 1][1],
                      ks_base + (row * AST + col) * 4);
            }
            uint32_t a[4];
            int row = warp_q + (lane & 15);
            int col = k8 + 4 * (lane >> 4);
            ldsm4(a[0], a[1], a[2], a[3], qs_base + (row * AST + col) * 4);
            #pragma unroll
            for (int nf = 0; nf < 8; nf++) mma8(sfr[nf], a, kb[nf]);
        }

        // Online softmax (base-2); row owned by 4 lanes (same gr)
        #pragma unroll
        for (int rr = 0; rr < 2; rr++) {
            float mx = -1e30f;
            #pragma unroll
            for (int nf = 0; nf < 8; nf++)
                mx = fmaxf(mx, fmaxf(sfr[nf][rr * 2], sfr[nf][rr * 2 + 1]));
            mx = fmaxf(mx, __shfl_xor_sync(0xffffffffu, mx, 1));
            mx = fmaxf(mx, __shfl_xor_sync(0xffffffffu, mx, 2));
            float mn = fmaxf(m_s[rr], mx);
            float al = ex2f(m_s[rr] - mn);
            m_s[rr] = mn;
            float rs = 0.f;
            #pragma unroll
            for (int nf = 0; nf < 8; nf++) {
                float p0 = ex2f(sfr[nf][rr * 2] - mn);
                float p1 = ex2f(sfr[nf][rr * 2 + 1] - mn);
                sfr[nf][rr * 2] = p0;
                sfr[nf][rr * 2 + 1] = p1;
                rs += p0 + p1;
                accO[nf][rr * 2] *= al;
                accO[nf][rr * 2 + 1] *= al;
            }
            rs += __shfl_xor_sync(0xffffffffu, rs, 1);
            rs += __shfl_xor_sync(0xffffffffu, rs, 2);
            l_s[rr] = l_s[rr] * al + rs;
        }

        // Store P (tf32) to warp-private Ps rows
        #pragma unroll
        for (int nf = 0; nf < 8; nf++) {
            int col = nf * 8 + 2 * tig;
            int rw = warp_q + gr;
            *(uint2*)(Ps + rw * AST + col) =
                make_uint2(f2tf(sfr[nf][0]), f2tf(sfr[nf][1]));
            *(uint2*)(Ps + (rw + 8) * AST + col) =
                make_uint2(f2tf(sfr[nf][2]), f2tf(sfr[nf][3]));
        }
        __syncwarp();

        // O += P V   (A = Ps[q][s], B = Vs[d][s])
        #pragma unroll
        for (int ks = 0; ks < 8; ks++) {
            int s8 = ks * 8;
            uint32_t vb[8][2];
            #pragma unroll
            for (int p = 0; p < 4; p++) {
                int row = 16 * p + (lane & 7) + ((lane >> 4) << 3);
                int col = s8 + 4 * ((lane >> 3) & 1);
                ldsm4(vb[2 * p][0], vb[2 * p][1], vb[2 * p + 1][0], vb[2 * p + 1][1],
                      vs_base + (row * AST + col) * 4);
            }
            uint32_t a[4];
            int row = warp_q + (lane & 15);
            int col = s8 + 4 * (lane >> 4);
            ldsm4(a[0], a[1], a[2], a[3], ps_base + (row * AST + col) * 4);
            #pragma unroll
            for (int nf = 0; nf < 8; nf++) mma8(accO[nf], a, vb[nf]);
        }
        __syncthreads();   // stage free before next issue
    }

    // Normalize and write ctx[t*2+b][h*64+d]
    const int bb = bh >> 4;
    const int h = bh & 15;
    #pragma unroll
    for (int rr = 0; rr < 2; rr++) {
        float inv = 1.0f / l_s[rr];
        int t = q0 + warp_q + gr + 8 * rr;
        #pragma unroll
        for (int nf = 0; nf < 8; nf++) {
            int d = nf * 8 + 2 * tig;
            *(float2*)(g_ctx + ((size_t)t * BATCH + bb) * EMBED + h * HDIM + d) =
                make_float2(accO[nf][rr * 2] * inv, accO[nf][rr * 2 + 1] * inv);
        }
    }
}

// ---------------------------------------------------------------------------
// Kernel 3: output projection (tf32 tensor core).  Same core as kernel 1.
// ---------------------------------------------------------------------------
__global__ __launch_bounds__(256, 2) void outproj_kernel(
    const float* __restrict__ w,      // [1024,1024]
    const float* __restrict__ bias,   // [1024]
    float* __restrict__ out)          // [4096,1024]
{
    __shared__ __align__(16) uint32_t As[128 * GST];
    __shared__ __align__(16) uint32_t Bs[128 * GST];

    const int bm = blockIdx.y * 128, bn = blockIdx.x * 128;
    const int tid = threadIdx.x, wid = tid >> 5, lane = tid & 31;
    const int gr = lane >> 2, tig = lane & 3;
    const int wm = (wid & 1) * 64, wn = (wid >> 1) * 32;
    const int r0 = tid >> 3, q = tid & 7;

    float acc[4][4][4];
    #pragma unroll
    for (int i = 0; i < 4; i++)
        #pragma unroll
        for (int j = 0; j < 4; j++)
            #pragma unroll
            for (int r = 0; r < 4; r++) acc[i][j][r] = 0.f;

    const float* ap = g_ctx + (size_t)(bm + r0) * EMBED + q * 4;
    const float* bp = w + (size_t)(bn + r0) * EMBED + q * 4;

    float4 pa[4], pb[4];
    #pragma unroll
    for (int it = 0; it < 4; it++) {
        pa[it] = *(const float4*)(ap + (size_t)it * 32 * EMBED);
        pb[it] = *(const float4*)(bp + (size_t)it * 32 * EMBED);
    }
    #pragma unroll
    for (int it = 0; it < 4; it++) {
        *(uint4*)(As + (r0 + 32 * it) * GST + q * 4) =
            make_uint4(f2tf(pa[it].x), f2tf(pa[it].y), f2tf(pa[it].z), f2tf(pa[it].w));
        *(uint4*)(Bs + (r0 + 32 * it) * GST + q * 4) =
            make_uint4(f2tf(pb[it].x), f2tf(pb[it].y), f2tf(pb[it].z), f2tf(pb[it].w));
    }
    __syncthreads();

    const uint32_t as_base = s2u(As), bs_base = s2u(Bs);

    #pragma unroll 1
    for (int kb = 0; kb < 32; kb++) {
        if (kb < 31) {
            int k0 = (kb + 1) * 32;
            #pragma unroll
            for (int it = 0; it < 4; it++) {
                pa[it] = *(const float4*)(ap + (size_t)it * 32 * EMBED + k0);
                pb[it] = *(const float4*)(bp + (size_t)it * 32 * EMBED + k0);
            }
        }
        #pragma unroll
        for (int ks = 0; ks < 4; ks++) {
            int k8 = ks * 8;
            uint32_t bfr[4][2];
            #pragma unroll
            for (int p = 0; p < 2; p++) {
                int row = wn + 16 * p + (lane & 7) + ((lane >> 4) << 3);
                int col = k8 + 4 * ((lane >> 3) & 1);
                ldsm4(bfr[2 * p][0], bfr[2 * p][1], bfr[2 * p + 1][0], bfr[2 * p + 1][1],
                      bs_base + (row * GST + col) * 4);
            }
            #pragma unroll
            for (int mi = 0; mi < 4; mi++) {
                uint32_t a[4];
                int row = wm + 16 * mi + (lane & 15);
                int col = k8 + 4 * (lane >> 4);
                ldsm4(a[0], a[1], a[2], a[3], as_base + (row * GST + col) * 4);
                #pragma unroll
                for (int nj = 0; nj < 4; nj++) mma8(acc[mi][nj], a, bfr[nj]);
            }
        }
        __syncthreads();
        if (kb < 31) {
            #pragma unroll
            for (int it = 0; it < 4; it++) {
                *(uint4*)(As + (r0 + 32 * it) * GST + q * 4) =
                    make_uint4(f2tf(pa[it].x), f2tf(pa[it].y), f2tf(pa[it].z), f2tf(pa[it].w));
                *(uint4*)(Bs + (r0 + 32 * it) * GST + q * 4) =
                    make_uint4(f2tf(pb[it].x), f2tf(pb[it].y), f2tf(pb[it].z), f2tf(pb[it].w));
            }
            __syncthreads();
        }
    }

    #pragma unroll
    for (int mi = 0; mi < 4; mi++)
        #pragma unroll
        for (int nj = 0; nj < 4; nj++)
            #pragma unroll
            for (int rr = 0; rr < 2; rr++) {
                int m = bm + wm + mi * 16 + gr + 8 * rr;
                int f = bn + wn + nj * 8 + 2 * tig;
                *(float2*)(out + (size_t)m * EMBED + f) =
                    make_float2(acc[mi][nj][rr * 2 + 0] + bias[f],
                                acc[mi][nj][rr * 2 + 1] + bias[f + 1]);
            }
}

// ---------------------------------------------------------------------------
extern "C" void kernel_launch(void* const* d_in, const int* in_sizes, int n_in,
                              void* d_out, int out_size)
{
    const float* x  = (const float*)d_in[0];   // [2048,2,1024]
    const float* w1 = (const float*)d_in[1];   // [3072,1024]
    const float* b1 = (const float*)d_in[2];   // [3072]
    const float* w2 = (const float*)d_in[3];   // [1024,1024]
    const float* b2 = (const float*)d_in[4];   // [1024]
    float* out = (float*)d_out;

    static bool attr_set = false;
    if (!attr_set) {
        cudaFuncSetAttribute(attn_kernel,
                             cudaFuncAttributeMaxDynamicSharedMemorySize, ATTN_SMEM);
        attr_set = true;
    }

    qkv_kernel<<<dim3(24, 32), 256>>>(x, w1, b1);
    attn_kernel<<<dim3(T_LEN / 128, BHEAD), 256, ATTN_SMEM>>>();
    outproj_kernel<<<dim3(8, 32), 256>>>(w2, b2, out);
}

// round 5
// speedup vs baseline: 1.1422x; 1.1422x over previous
#include <cuda_runtime.h>
#include <cuda_bf16.h>
#include <cstdint>

// Problem constants
#define T_LEN 2048
#define BATCH 2
#define EMBED 1024
#define NHEAD 16
#define HDIM  64
#define BHEAD (BATCH * NHEAD)          // 32
#define NTOK  (T_LEN * BATCH)          // 4096
// 0.125 (=64^-0.5) * log2(e): softmax computed in base-2 domain
#define QSCALE 0.18033688011112042f

// Scratch (allocation-free rule: __device__ globals).
// q/k/v stored as pre-converted tf32 bit patterns; v transposed [bh][d][t].
__device__ __align__(16) uint32_t g_qb[BHEAD * T_LEN * HDIM];  // [bh][t][d] (pre-scaled)
__device__ __align__(16) uint32_t g_kb[BHEAD * T_LEN * HDIM];  // [bh][t][d]
__device__ __align__(16) uint32_t g_vb[BHEAD * T_LEN * HDIM];  // [bh][d][t]
__device__ __align__(16) float    g_ctx[NTOK * EMBED];         // [t*2+b][e]

// ---------------------------------------------------------------------------
// PTX helpers
// ---------------------------------------------------------------------------
__device__ __forceinline__ uint32_t s2u(const void* p) {
    return (uint32_t)__cvta_generic_to_shared(p);
}
__device__ __forceinline__ uint32_t f2tf(float x) {
    uint32_t r; asm("cvt.rna.tf32.f32 %0, %1;" : "=r"(r) : "f"(x)); return r;
}
__device__ __forceinline__ float ex2f(float x) {
    float r; asm("ex2.approx.f32 %0, %1;" : "=f"(r) : "f"(x)); return r;
}
__device__ __forceinline__ void ldsm4(uint32_t& r0, uint32_t& r1, uint32_t& r2,
                                      uint32_t& r3, uint32_t addr) {
    asm volatile("ldmatrix.sync.aligned.m8n8.x4.shared.b16 {%0,%1,%2,%3}, [%4];"
                 : "=r"(r0), "=r"(r1), "=r"(r2), "=r"(r3) : "r"(addr));
}
__device__ __forceinline__ void mma8(float* c, const uint32_t* a, const uint32_t* b) {
    asm volatile(
        "mma.sync.aligned.m16n8k8.row.col.f32.tf32.tf32.f32 "
        "{%0,%1,%2,%3}, {%4,%5,%6,%7}, {%8,%9}, {%0,%1,%2,%3};\n"
        : "+f"(c[0]), "+f"(c[1]), "+f"(c[2]), "+f"(c[3])
        : "r"(a[0]), "r"(a[1]), "r"(a[2]), "r"(a[3]), "r"(b[0]), "r"(b[1]));
}
__device__ __forceinline__ void cpasync16(uint32_t dst, const void* src) {
    asm volatile("cp.async.cg.shared.global [%0], [%1], 16;" :: "r"(dst), "l"(src));
}
#define CP_COMMIT() asm volatile("cp.async.commit_group;")

// ---------------------------------------------------------------------------
// Kernel 1: QKV projection (tf32 tensor core).
// Block 128x128, BK=32, 256 threads = 8 warps, warp tile 64x32.
// Epilogue: bias; q pre-scale; all outputs stored as tf32 bits; V blocks are
// staged through smem and written transposed ([bh][d][t]) fully coalesced.
// ---------------------------------------------------------------------------
#define GST 36

__global__ __launch_bounds__(256) void qkv_kernel(
    const float* __restrict__ x,      // [4096,1024]
    const float* __restrict__ w,      // [3072,1024]
    const float* __restrict__ bias)   // [3072]
{
    __shared__ __align__(16) uint32_t smem_all[2 * 128 * GST];
    uint32_t* As = smem_all;
    uint32_t* Bs = smem_all + 128 * GST;

    const int bm = blockIdx.y * 128, bn = blockIdx.x * 128;
    const int tid = threadIdx.x, wid = tid >> 5, lane = tid & 31;
    const int gr = lane >> 2, tig = lane & 3;
    const int wm = (wid & 1) * 64, wn = (wid >> 1) * 32;
    const int r0 = tid >> 3, q = tid & 7;

    float acc[4][4][4];
    #pragma unroll
    for (int i = 0; i < 4; i++)
        #pragma unroll
        for (int j = 0; j < 4; j++)
            #pragma unroll
            for (int r = 0; r < 4; r++) acc[i][j][r] = 0.f;

    const float* ap = x + (size_t)(bm + r0) * EMBED + q * 4;
    const float* bp = w + (size_t)(bn + r0) * EMBED + q * 4;

    float4 pa[4], pb[4];
    #pragma unroll
    for (int it = 0; it < 4; it++) {
        pa[it] = *(const float4*)(ap + (size_t)it * 32 * EMBED);
        pb[it] = *(const float4*)(bp + (size_t)it * 32 * EMBED);
    }
    #pragma unroll
    for (int it = 0; it < 4; it++) {
        *(uint4*)(As + (r0 + 32 * it) * GST + q * 4) =
            make_uint4(f2tf(pa[it].x), f2tf(pa[it].y), f2tf(pa[it].z), f2tf(pa[it].w));
        *(uint4*)(Bs + (r0 + 32 * it) * GST + q * 4) =
            make_uint4(f2tf(pb[it].x), f2tf(pb[it].y), f2tf(pb[it].z), f2tf(pb[it].w));
    }
    __syncthreads();

    const uint32_t as_base = s2u(As), bs_base = s2u(Bs);

    #pragma unroll 1
    for (int kb = 0; kb < 32; kb++) {
        if (kb < 31) {
            int k0 = (kb + 1) * 32;
            #pragma unroll
            for (int it = 0; it < 4; it++) {
                pa[it] = *(const float4*)(ap + (size_t)it * 32 * EMBED + k0);
                pb[it] = *(const float4*)(bp + (size_t)it * 32 * EMBED + k0);
            }
        }
        #pragma unroll
        for (int ks = 0; ks < 4; ks++) {
            int k8 = ks * 8;
            uint32_t bfr[4][2];
            #pragma unroll
            for (int p = 0; p < 2; p++) {
                int row = wn + 16 * p + (lane & 7) + ((lane >> 4) << 3);
                int col = k8 + 4 * ((lane >> 3) & 1);
                ldsm4(bfr[2 * p][0], bfr[2 * p][1], bfr[2 * p + 1][0], bfr[2 * p + 1][1],
                      bs_base + (row * GST + col) * 4);
            }
            #pragma unroll
            for (int mi = 0; mi < 4; mi++) {
                uint32_t a[4];
                int row = wm + 16 * mi + (lane & 15);
                int col = k8 + 4 * (lane >> 4);
                ldsm4(a[0], a[1], a[2], a[3], as_base + (row * GST + col) * 4);
                #pragma unroll
                for (int nj = 0; nj < 4; nj++) mma8(acc[mi][nj], a, bfr[nj]);
            }
        }
        __syncthreads();
        if (kb < 31) {
            #pragma unroll
            for (int it = 0; it < 4; it++) {
                *(uint4*)(As + (r0 + 32 * it) * GST + q * 4) =
                    make_uint4(f2tf(pa[it].x), f2tf(pa[it].y), f2tf(pa[it].z), f2tf(pa[it].w));
                *(uint4*)(Bs + (r0 + 32 * it) * GST + q * 4) =
                    make_uint4(f2tf(pb[it].x), f2tf(pb[it].y), f2tf(pb[it].z), f2tf(pb[it].w));
            }
            __syncthreads();
        }
    }

    const int which = bn >> 10;        // uniform per CTA (bn 128-aligned)

    if (which < 2) {
        // Direct q/k writes: [bh][t][d], tf32 bits
        #pragma unroll
        for (int mi = 0; mi < 4; mi++)
            #pragma unroll
            for (int nj = 0; nj < 4; nj++)
                #pragma unroll
                for (int rr = 0; rr < 2; rr++) {
                    int m = bm + wm + mi * 16 + gr + 8 * rr;
                    int f = bn + wn + nj * 8 + 2 * tig;
                    float c0 = acc[mi][nj][rr * 2 + 0] + bias[f];
                    float c1 = acc[mi][nj][rr * 2 + 1] + bias[f + 1];
                    int hd = f & 1023, h = hd >> 6, d = hd & 63;
                    int t = m >> 1, bb = m & 1;
                    int bh = bb * NHEAD + h;
                    if (which == 0) {
                        *(uint2*)(g_qb + ((size_t)bh * T_LEN + t) * HDIM + d) =
                            make_uint2(f2tf(c0 * QSCALE), f2tf(c1 * QSCALE));
                    } else {
                        *(uint2*)(g_kb + ((size_t)bh * T_LEN + t) * HDIM + d) =
                            make_uint2(f2tf(c0), f2tf(c1));
                    }
                }
    } else {
        // V: stage [f_local][m_local] in smem, write coalesced to [bh][d][t].
        // Two passes of 64 f-rows (64 x 130 words fits in As+Bs).
        uint32_t* S = smem_all;               // stride 130
        const int hbase = (bn - 2048) >> 6;
        const int t0 = bm >> 1;
        #pragma unroll 1
        for (int pass = 0; pass < 2; pass++) {
            if ((wn >> 6) == pass) {
                #pragma unroll
                for (int mi = 0; mi < 4; mi++)
                    #pragma unroll
                    for (int nj = 0; nj < 4; nj++)
                        #pragma unroll
                        for (int rr = 0; rr < 2; rr++) {
                            int fl = wn + nj * 8 + 2 * tig;      // f_local 0..127
                            int f2 = fl & 63;
                            int ml = wm + mi * 16 + gr + 8 * rr;
                            float c0 = acc[mi][nj][rr * 2 + 0] + bias[bn + fl];
                            float c1 = acc[mi][nj][rr * 2 + 1] + bias[bn + fl + 1];
                            S[f2 * 130 + ml] = f2tf(c0);
                            S[(f2 + 1) * 130 + ml] = f2tf(c1);
                        }
            }
            __syncthreads();
            int h = hbase + pass;
            #pragma unroll
            for (int i = 0; i < 32; i++) {
                int idx = tid + 256 * i;       // 0..8191
                int bb = idx >> 12;
                int rem = idx & 4095;
                int d = rem >> 6;
                int tl = rem & 63;
                g_vb[(((size_t)(bb * NHEAD + h)) * HDIM + d) * T_LEN + t0 + tl] =
                    S[d * 130 + 2 * tl + bb];
            }
            __syncthreads();
        }
    }
}

// ---------------------------------------------------------------------------
// Kernel 2: flash attention (tf32 tensor core), cp.async double-buffered.
// Block = (bh, 128-query tile), 128 threads = 4 warps; warp owns 32 q-rows.
// Q is held in A-fragment REGISTERS (loop-invariant), staged once through the
// KV smem region.  Smem: Ps[128][68] + 2 stages of (K[64][68] | V[64][68]).
// 102KB -> 2 CTAs/SM.  Softmax in base-2 domain.
// ---------------------------------------------------------------------------
#define AST 68
#define ATTN_SMEM ((128 + 2 * 128) * AST * 4)

__global__ __launch_bounds__(128) void attn_kernel()
{
    extern __shared__ uint32_t sm[];
    uint32_t* Ps = sm;                    // [128][68]
    uint32_t* KV = Ps + 128 * AST;        // 2 stages x 128 rows x 68

    const int bh = blockIdx.y;
    const int q0 = blockIdx.x * 128;
    const int tid = threadIdx.x, wid = tid >> 5, lane = tid & 31;
    const int gr = lane >> 2, tig = lane & 3;
    const int warp_q = wid * 32;

    const uint32_t* qg = g_qb + (size_t)bh * T_LEN * HDIM;
    const uint32_t* kg = g_kb + (size_t)bh * T_LEN * HDIM;
    const uint32_t* vg = g_vb + (size_t)bh * T_LEN * HDIM;  // [d][t]

    // --- Prologue: stage Q tile (128x64) into KV stage-0, ldsm into regs ---
    {
        #pragma unroll
        for (int j = 0; j < 16; j++) {
            int id = tid + 128 * j;            // 2048 float4s
            int r = id >> 4, c4 = (id & 15) * 4;
            cpasync16(s2u(KV + r * AST + c4), qg + (size_t)(q0 + r) * HDIM + c4);
        }
        CP_COMMIT();
        asm volatile("cp.async.wait_group 0;");
        __syncthreads();
    }
    uint32_t qf[2][8][4];
    {
        const uint32_t q_base = s2u(KV);
        #pragma unroll
        for (int mi = 0; mi < 2; mi++)
            #pragma unroll
            for (int ks = 0; ks < 8; ks++) {
                int row = warp_q + mi * 16 + (lane & 15);
                int col = ks * 8 + 4 * (lane >> 4);
                ldsm4(qf[mi][ks][0], qf[mi][ks][1], qf[mi][ks][2], qf[mi][ks][3],
                      q_base + (row * AST + col) * 4);
            }
    }
    __syncthreads();   // Q region free -> becomes KV stage 0

    // Preload K/V tile 0 into stage 0  (K rows 0..63, V rows 64..127)
    #pragma unroll
    for (int j = 0; j < 8; j++) {
        int id = tid + 128 * j;
        int row = id >> 4, c4 = (id & 15) * 4;
        cpasync16(s2u(KV + row * AST + c4), kg + (size_t)row * HDIM + c4);
        cpasync16(s2u(KV + (64 + row) * AST + c4), vg + (size_t)row * T_LEN + c4);
    }
    CP_COMMIT();

    float accO[2][8][4];
    #pragma unroll
    for (int mi = 0; mi < 2; mi++)
        #pragma unroll
        for (int nf = 0; nf < 8; nf++)
            #pragma unroll
            for (int r = 0; r < 4; r++) accO[mi][nf][r] = 0.f;
    float m_s[2][2] = {{-1e30f, -1e30f}, {-1e30f, -1e30f}};
    float l_s[2][2] = {{0.f, 0.f}, {0.f, 0.f}};

    const uint32_t ps_base = s2u(Ps);

    #pragma unroll 1
    for (int it = 0; it < T_LEN / 64; it++) {
        int cur = it & 1;
        if (it < T_LEN / 64 - 1) {
            int s0 = (it + 1) * 64;
            uint32_t* Kn = KV + (1 - cur) * 128 * AST;
            #pragma unroll
            for (int j = 0; j < 8; j++) {
                int id = tid + 128 * j;
                int row = id >> 4, c4 = (id & 15) * 4;
                cpasync16(s2u(Kn + row * AST + c4), kg + (size_t)(s0 + row) * HDIM + c4);
                cpasync16(s2u(Kn + (64 + row) * AST + c4),
                          vg + (size_t)row * T_LEN + s0 + c4);
            }
            CP_COMMIT();
            asm volatile("cp.async.wait_group 1;");
        } else {
            asm volatile("cp.async.wait_group 0;");
        }
        __syncthreads();

        const uint32_t ks_base = s2u(KV + cur * 128 * AST);
        const uint32_t vs_base = ks_base + 64 * AST * 4;

        // S = Q K^T  (warp: 32 q-rows x 64 keys); Q from registers
        float sfr[2][8][4];
        #pragma unroll
        for (int mi = 0; mi < 2; mi++)
            #pragma unroll
            for (int nf = 0; nf < 8; nf++)
                #pragma unroll
                for (int r = 0; r < 4; r++) sfr[mi][nf][r] = 0.f;

        #pragma unroll
        for (int ks = 0; ks < 8; ks++) {
            int k8 = ks * 8;
            uint32_t kb[8][2];
            #pragma unroll
            for (int p = 0; p < 4; p++) {
                int row = 16 * p + (lane & 7) + ((lane >> 4) << 3);
                int col = k8 + 4 * ((lane >> 3) & 1);
                ldsm4(kb[2 * p][0], kb[2 * p][1], kb[2 * p + 1][0], kb[2 * p + 1][1],
                      ks_base + (row * AST + col) * 4);
            }
            #pragma unroll
            for (int mi = 0; mi < 2; mi++)
                #pragma unroll
                for (int nf = 0; nf < 8; nf++) mma8(sfr[mi][nf], qf[mi][ks], kb[nf]);
        }

        // Online softmax (base-2); row owned by 4 lanes (same gr)
        #pragma unroll
        for (int mi = 0; mi < 2; mi++)
            #pragma unroll
            for (int rr = 0; rr < 2; rr++) {
                float mx = -1e30f;
                #pragma unroll
                for (int nf = 0; nf < 8; nf++)
                    mx = fmaxf(mx, fmaxf(sfr[mi][nf][rr * 2], sfr[mi][nf][rr * 2 + 1]));
                mx = fmaxf(mx, __shfl_xor_sync(0xffffffffu, mx, 1));
                mx = fmaxf(mx, __shfl_xor_sync(0xffffffffu, mx, 2));
                float mn = fmaxf(m_s[mi][rr], mx);
                float al = ex2f(m_s[mi][rr] - mn);
                m_s[mi][rr] = mn;
                float rs = 0.f;
                #pragma unroll
                for (int nf = 0; nf < 8; nf++) {
                    float p0 = ex2f(sfr[mi][nf][rr * 2] - mn);
                    float p1 = ex2f(sfr[mi][nf][rr * 2 + 1] - mn);
                    sfr[mi][nf][rr * 2] = p0;
                    sfr[mi][nf][rr * 2 + 1] = p1;
                    rs += p0 + p1;
                    accO[mi][nf][rr * 2] *= al;
                    accO[mi][nf][rr * 2 + 1] *= al;
                }
                rs += __shfl_xor_sync(0xffffffffu, rs, 1);
                rs += __shfl_xor_sync(0xffffffffu, rs, 2);
                l_s[mi][rr] = l_s[mi][rr] * al + rs;
            }

        // Store P (tf32) to warp-private Ps rows
        #pragma unroll
        for (int mi = 0; mi < 2; mi++)
            #pragma unroll
            for (int nf = 0; nf < 8; nf++) {
                int col = nf * 8 + 2 * tig;
                int rw = warp_q + mi * 16 + gr;
                *(uint2*)(Ps + rw * AST + col) =
                    make_uint2(f2tf(sfr[mi][nf][0]), f2tf(sfr[mi][nf][1]));
                *(uint2*)(Ps + (rw + 8) * AST + col) =
                    make_uint2(f2tf(sfr[mi][nf][2]), f2tf(sfr[mi][nf][3]));
            }
        __syncwarp();

        // O += P V   (A = Ps[q][s], B = V[d][s])
        #pragma unroll
        for (int ks = 0; ks < 8; ks++) {
            int s8 = ks * 8;
            uint32_t vb[8][2];
            #pragma unroll
            for (int p = 0; p < 4; p++) {
                int row = 16 * p + (lane & 7) + ((lane >> 4) << 3);
                int col = s8 + 4 * ((lane >> 3) & 1);
                ldsm4(vb[2 * p][0], vb[2 * p][1], vb[2 * p + 1][0], vb[2 * p + 1][1],
                      vs_base + (row * AST + col) * 4);
            }
            #pragma unroll
            for (int mi = 0; mi < 2; mi++) {
                uint32_t a[4];
                int row = warp_q + mi * 16 + (lane & 15);
                int col = s8 + 4 * (lane >> 4);
                ldsm4(a[0], a[1], a[2], a[3], ps_base + (row * AST + col) * 4);
                #pragma unroll
                for (int nf = 0; nf < 8; nf++) mma8(accO[mi][nf], a, vb[nf]);
            }
        }
        __syncthreads();   // all reads of stage `cur` done before next issue
    }

    // Normalize and write ctx[t*2+b][h*64+d]
    const int bb = bh >> 4;
    const int h = bh & 15;
    #pragma unroll
    for (int mi = 0; mi < 2; mi++)
        #pragma unroll
        for (int rr = 0; rr < 2; rr++) {
            float inv = 1.0f / l_s[mi][rr];
            int t = q0 + warp_q + mi * 16 + gr + 8 * rr;
            #pragma unroll
            for (int nf = 0; nf < 8; nf++) {
                int d = nf * 8 + 2 * tig;
                *(float2*)(g_ctx + ((size_t)t * BATCH + bb) * EMBED + h * HDIM + d) =
                    make_float2(accO[mi][nf][rr * 2] * inv,
                                accO[mi][nf][rr * 2 + 1] * inv);
            }
        }
}

// ---------------------------------------------------------------------------
// Kernel 3: output projection (tf32 tensor core).  Same core as kernel 1.
// ---------------------------------------------------------------------------
__global__ __launch_bounds__(256) void outproj_kernel(
    const float* __restrict__ w,      // [1024,1024]
    const float* __restrict__ bias,   // [1024]
    float* __restrict__ out)          // [4096,1024]
{
    __shared__ __align__(16) uint32_t As[128 * GST];
    __shared__ __align__(16) uint32_t Bs[128 * GST];

    const int bm = blockIdx.y * 128, bn = blockIdx.x * 128;
    const int tid = threadIdx.x, wid = tid >> 5, lane = tid & 31;
    const int gr = lane >> 2, tig = lane & 3;
    const int wm = (wid & 1) * 64, wn = (wid >> 1) * 32;
    const int r0 = tid >> 3, q = tid & 7;

    float acc[4][4][4];
    #pragma unroll
    for (int i = 0; i < 4; i++)
        #pragma unroll
        for (int j = 0; j < 4; j++)
            #pragma unroll
            for (int r = 0; r < 4; r++) acc[i][j][r] = 0.f;

    const float* ap = g_ctx + (size_t)(bm + r0) * EMBED + q * 4;
    const float* bp = w + (size_t)(bn + r0) * EMBED + q * 4;

    float4 pa[4], pb[4];
    #pragma unroll
    for (int it = 0; it < 4; it++) {
        pa[it] = *(const float4*)(ap + (size_t)it * 32 * EMBED);
        pb[it] = *(const float4*)(bp + (size_t)it * 32 * EMBED);
    }
    #pragma unroll
    for (int it = 0; it < 4; it++) {
        *(uint4*)(As + (r0 + 32 * it) * GST + q * 4) =
            make_uint4(f2tf(pa[it].x), f2tf(pa[it].y), f2tf(pa[it].z), f2tf(pa[it].w));
        *(uint4*)(Bs + (r0 + 32 * it) * GST + q * 4) =
            make_uint4(f2tf(pb[it].x), f2tf(pb[it].y), f2tf(pb[it].z), f2tf(pb[it].w));
    }
    __syncthreads();

    const uint32_t as_base = s2u(As), bs_base = s2u(Bs);

    #pragma unroll 1
    for (int kb = 0; kb < 32; kb++) {
        if (kb < 31) {
            int k0 = (kb + 1) * 32;
            #pragma unroll
            for (int it = 0; it < 4; it++) {
                pa[it] = *(const float4*)(ap + (size_t)it * 32 * EMBED + k0);
                pb[it] = *(const float4*)(bp + (size_t)it * 32 * EMBED + k0);
            }
        }
        #pragma unroll
        for (int ks = 0; ks < 4; ks++) {
            int k8 = ks * 8;
            uint32_t bfr[4][2];
            #pragma unroll
            for (int p = 0; p < 2; p++) {
                int row = wn + 16 * p + (lane & 7) + ((lane >> 4) << 3);
                int col = k8 + 4 * ((lane >> 3) & 1);
                ldsm4(bfr[2 * p][0], bfr[2 * p][1], bfr[2 * p + 1][0], bfr[2 * p + 1][1],
                      bs_base + (row * GST + col) * 4);
            }
            #pragma unroll
            for (int mi = 0; mi < 4; mi++) {
                uint32_t a[4];
                int row = wm + 16 * mi + (lane & 15);
                int col = k8 + 4 * (lane >> 4);
                ldsm4(a[0], a[1], a[2], a[3], as_base + (row * GST + col) * 4);
                #pragma unroll
                for (int nj = 0; nj < 4; nj++) mma8(acc[mi][nj], a, bfr[nj]);
            }
        }
        __syncthreads();
        if (kb < 31) {
            #pragma unroll
            for (int it = 0; it < 4; it++) {
                *(uint4*)(As + (r0 + 32 * it) * GST + q * 4) =
                    make_uint4(f2tf(pa[it].x), f2tf(pa[it].y), f2tf(pa[it].z), f2tf(pa[it].w));
                *(uint4*)(Bs + (r0 + 32 * it) * GST + q * 4) =
                    make_uint4(f2tf(pb[it].x), f2tf(pb[it].y), f2tf(pb[it].z), f2tf(pb[it].w));
            }
            __syncthreads();
        }
    }

    #pragma unroll
    for (int mi = 0; mi < 4; mi++)
        #pragma unroll
        for (int nj = 0; nj < 4; nj++)
            #pragma unroll
            for (int rr = 0; rr < 2; rr++) {
                int m = bm + wm + mi * 16 + gr + 8 * rr;
                int f = bn + wn + nj * 8 + 2 * tig;
                *(float2*)(out + (size_t)m * EMBED + f) =
                    make_float2(acc[mi][nj][rr * 2 + 0] + bias[f],
                                acc[mi][nj][rr * 2 + 1] + bias[f + 1]);
            }
}

// ---------------------------------------------------------------------------
extern "C" void kernel_launch(void* const* d_in, const int* in_sizes, int n_in,
                              void* d_out, int out_size)
{
    const float* x  = (const float*)d_in[0];   // [2048,2,1024]
    const float* w1 = (const float*)d_in[1];   // [3072,1024]
    const float* b1 = (const float*)d_in[2];   // [3072]
    const float* w2 = (const float*)d_in[3];   // [1024,1024]
    const float* b2 = (const float*)d_in[4];   // [1024]
    float* out = (float*)d_out;

    static bool attr_set = false;
    if (!attr_set) {
        cudaFuncSetAttribute(attn_kernel,
                             cudaFuncAttributeMaxDynamicSharedMemorySize, ATTN_SMEM);
        attr_set = true;
    }

    qkv_kernel<<<dim3(24, 32), 256>>>(x, w1, b1);
    attn_kernel<<<dim3(T_LEN / 128, BHEAD), 128, ATTN_SMEM>>>();
    outproj_kernel<<<dim3(8, 32), 256>>>(w2, b2, out);
}

// round 7
// speedup vs baseline: 1.2393x; 1.0850x over previous
#include <cuda_runtime.h>
#include <cuda_bf16.h>
#include <cstdint>

// Problem constants
#define T_LEN 2048
#define BATCH 2
#define EMBED 1024
#define NHEAD 16
#define HDIM  64
#define BHEAD (BATCH * NHEAD)          // 32
#define NTOK  (T_LEN * BATCH)          // 4096
// 0.125 (=64^-0.5) * log2(e): softmax computed in base-2 domain
#define QSCALE 0.18033688011112042f

// Scratch (allocation-free rule: __device__ globals).
// q/k/v stored as pre-converted tf32 bit patterns.
__device__ __align__(16) uint32_t g_qb[BHEAD * T_LEN * HDIM];  // [bh][t][d] (pre-scaled)
__device__ __align__(16) uint32_t g_kb[BHEAD * T_LEN * HDIM];  // [bh][t][d]
__device__ __align__(16) uint32_t g_vn[BHEAD * T_LEN * HDIM];  // [bh][t][d] natural
__device__ __align__(16) uint32_t g_vb[BHEAD * T_LEN * HDIM];  // [bh][d][t] transposed
__device__ __align__(16) float    g_ctx[NTOK * EMBED];         // [t*2+b][e]

// ---------------------------------------------------------------------------
// PTX helpers
// ---------------------------------------------------------------------------
__device__ __forceinline__ uint32_t s2u(const void* p) {
    return (uint32_t)__cvta_generic_to_shared(p);
}
__device__ __forceinline__ uint32_t f2tf(float x) {
    uint32_t r; asm("cvt.rna.tf32.f32 %0, %1;" : "=r"(r) : "f"(x)); return r;
}
__device__ __forceinline__ float ex2f(float x) {
    float r; asm("ex2.approx.f32 %0, %1;" : "=f"(r) : "f"(x)); return r;
}
__device__ __forceinline__ void ldsm4(uint32_t& r0, uint32_t& r1, uint32_t& r2,
                                      uint32_t& r3, uint32_t addr) {
    asm volatile("ldmatrix.sync.aligned.m8n8.x4.shared.b16 {%0,%1,%2,%3}, [%4];"
                 : "=r"(r0), "=r"(r1), "=r"(r2), "=r"(r3) : "r"(addr));
}
__device__ __forceinline__ void mma8(float* c, const uint32_t* a, const uint32_t* b) {
    asm volatile(
        "mma.sync.aligned.m16n8k8.row.col.f32.tf32.tf32.f32 "
        "{%0,%1,%2,%3}, {%4,%5,%6,%7}, {%8,%9}, {%0,%1,%2,%3};\n"
        : "+f"(c[0]), "+f"(c[1]), "+f"(c[2]), "+f"(c[3])
        : "r"(a[0]), "r"(a[1]), "r"(a[2]), "r"(a[3]), "r"(b[0]), "r"(b[1]));
}
__device__ __forceinline__ void cpasync16(uint32_t dst, const void* src) {
    asm volatile("cp.async.cg.shared.global [%0], [%1], 16;" :: "r"(dst), "l"(src));
}
#define CP_COMMIT() asm volatile("cp.async.commit_group;")

// ---------------------------------------------------------------------------
// Kernel 1: QKV projection (tf32 tensor core).
// Block 128x128, BK=32, 256 threads = 8 warps, warp tile 64x32.
// Lean epilogue (regs ~128, 2 CTAs/SM): bias, q pre-scale, tf32 bits,
// direct uint2 scatter.  V written NATURALLY; transpose is a separate kernel.
// ---------------------------------------------------------------------------
#define GST 36

__global__ __launch_bounds__(256) void qkv_kernel(
    const float* __restrict__ x,      // [4096,1024]
    const float* __restrict__ w,      // [3072,1024]
    const float* __restrict__ bias)   // [3072]
{
    __shared__ __align__(16) uint32_t As[128 * GST];
    __shared__ __align__(16) uint32_t Bs[128 * GST];

    const int bm = blockIdx.y * 128, bn = blockIdx.x * 128;
    const int tid = threadIdx.x, wid = tid >> 5, lane = tid & 31;
    const int gr = lane >> 2, tig = lane & 3;
    const int wm = (wid & 1) * 64, wn = (wid >> 1) * 32;
    const int r0 = tid >> 3, q = tid & 7;

    float acc[4][4][4];
    #pragma unroll
    for (int i = 0; i < 4; i++)
        #pragma unroll
        for (int j = 0; j < 4; j++)
            #pragma unroll
            for (int r = 0; r < 4; r++) acc[i][j][r] = 0.f;

    const float* ap = x + (size_t)(bm + r0) * EMBED + q * 4;
    const float* bp = w + (size_t)(bn + r0) * EMBED + q * 4;

    float4 pa[4], pb[4];
    #pragma unroll
    for (int it = 0; it < 4; it++) {
        pa[it] = *(const float4*)(ap + (size_t)it * 32 * EMBED);
        pb[it] = *(const float4*)(bp + (size_t)it * 32 * EMBED);
    }
    #pragma unroll
    for (int it = 0; it < 4; it++) {
        *(uint4*)(As + (r0 + 32 * it) * GST + q * 4) =
            make_uint4(f2tf(pa[it].x), f2tf(pa[it].y), f2tf(pa[it].z), f2tf(pa[it].w));
        *(uint4*)(Bs + (r0 + 32 * it) * GST + q * 4) =
            make_uint4(f2tf(pb[it].x), f2tf(pb[it].y), f2tf(pb[it].z), f2tf(pb[it].w));
    }
    __syncthreads();

    const uint32_t as_base = s2u(As), bs_base = s2u(Bs);

    #pragma unroll 1
    for (int kb = 0; kb < 32; kb++) {
        if (kb < 31) {
            int k0 = (kb + 1) * 32;
            #pragma unroll
            for (int it = 0; it < 4; it++) {
                pa[it] = *(const float4*)(ap + (size_t)it * 32 * EMBED + k0);
                pb[it] = *(const float4*)(bp + (size_t)it * 32 * EMBED + k0);
            }
        }
        #pragma unroll
        for (int ks = 0; ks < 4; ks++) {
            int k8 = ks * 8;
            uint32_t bfr[4][2];
            #pragma unroll
            for (int p = 0; p < 2; p++) {
                int row = wn + 16 * p + (lane & 7) + ((lane >> 4) << 3);
                int col = k8 + 4 * ((lane >> 3) & 1);
                ldsm4(bfr[2 * p][0], bfr[2 * p][1], bfr[2 * p + 1][0], bfr[2 * p + 1][1],
                      bs_base + (row * GST + col) * 4);
            }
            #pragma unroll
            for (int mi = 0; mi < 4; mi++) {
                uint32_t a[4];
                int row = wm + 16 * mi + (lane & 15);
                int col = k8 + 4 * (lane >> 4);
                ldsm4(a[0], a[1], a[2], a[3], as_base + (row * GST + col) * 4);
                #pragma unroll
                for (int nj = 0; nj < 4; nj++) mma8(acc[mi][nj], a, bfr[nj]);
            }
        }
        __syncthreads();
        if (kb < 31) {
            #pragma unroll
            for (int it = 0; it < 4; it++) {
                *(uint4*)(As + (r0 + 32 * it) * GST + q * 4) =
                    make_uint4(f2tf(pa[it].x), f2tf(pa[it].y), f2tf(pa[it].z), f2tf(pa[it].w));
                *(uint4*)(Bs + (r0 + 32 * it) * GST + q * 4) =
                    make_uint4(f2tf(pb[it].x), f2tf(pb[it].y), f2tf(pb[it].z), f2tf(pb[it].w));
            }
            __syncthreads();
        }
    }

    // Lean epilogue: bias, q pre-scale, tf32 bits, direct scatter
    #pragma unroll
    for (int mi = 0; mi < 4; mi++)
        #pragma unroll
        for (int nj = 0; nj < 4; nj++)
            #pragma unroll
            for (int rr = 0; rr < 2; rr++) {
                int m = bm + wm + mi * 16 + gr + 8 * rr;
                int f = bn + wn + nj * 8 + 2 * tig;
                float c0 = acc[mi][nj][rr * 2 + 0] + bias[f];
                float c1 = acc[mi][nj][rr * 2 + 1] + bias[f + 1];
                int which = f >> 10, hd = f & 1023, h = hd >> 6, d = hd & 63;
                int t = m >> 1, bb = m & 1;
                int bh = bb * NHEAD + h;
                size_t off = ((size_t)bh * T_LEN + t) * HDIM + d;
                if (which == 0) {
                    *(uint2*)(g_qb + off) = make_uint2(f2tf(c0 * QSCALE), f2tf(c1 * QSCALE));
                } else if (which == 1) {
                    *(uint2*)(g_kb + off) = make_uint2(f2tf(c0), f2tf(c1));
                } else {
                    *(uint2*)(g_vn + off) = make_uint2(f2tf(c0), f2tf(c1));
                }
            }
}

// ---------------------------------------------------------------------------
// Kernel 1b: V transpose.  g_vn[bh][t][d] -> g_vb[bh][d][t].
// 64x64 tiles; global accesses are uint4 coalesced, smem accesses are SCALAR
// with odd stride 65 (bank-conflict-free, and no 16B-alignment hazard).
// ---------------------------------------------------------------------------
__global__ __launch_bounds__(256) void vtrans_kernel()
{
    __shared__ uint32_t S[64 * 65];     // [d][t], stride 65 (odd)
    const int bh = blockIdx.y;
    const int t0 = blockIdx.x * 64;
    const int tid = threadIdx.x;
    const int r0 = tid >> 4, c4 = (tid & 15) * 4;

    const uint32_t* src = g_vn + (size_t)bh * T_LEN * HDIM;
    uint32_t* dst = g_vb + (size_t)bh * T_LEN * HDIM;   // [d][t]

    // Load 64 t-rows x 64 d (uint4 from global), scatter scalars into S[d][t]
    #pragma unroll
    for (int i = 0; i < 4; i++) {
        int t = r0 + 16 * i;
        uint4 v = *(const uint4*)(src + (size_t)(t0 + t) * HDIM + c4);
        S[(c4 + 0) * 65 + t] = v.x;
        S[(c4 + 1) * 65 + t] = v.y;
        S[(c4 + 2) * 65 + t] = v.z;
        S[(c4 + 3) * 65 + t] = v.w;
    }
    __syncthreads();

    // Gather scalars from S rows (d-major), write uint4 coalesced along t
    #pragma unroll
    for (int i = 0; i < 4; i++) {
        int d = r0 + 16 * i;
        uint4 o;
        o.x = S[d * 65 + c4 + 0];
        o.y = S[d * 65 + c4 + 1];
        o.z = S[d * 65 + c4 + 2];
        o.w = S[d * 65 + c4 + 3];
        *(uint4*)(dst + (size_t)d * T_LEN + t0 + c4) = o;
    }
}

// ---------------------------------------------------------------------------
// Kernel 2: flash attention (tf32 tensor core), cp.async double-buffered.
// Block = (bh, 128-query tile), 128 threads = 4 warps; warp owns 32 q-rows.
// Q held in A-fragment registers (loop-invariant), staged once through smem.
// Smem: Ps[128][68] + 2 stages of (K[64][68] | V[64][68]).  2 CTAs/SM.
// ---------------------------------------------------------------------------
#define AST 68
#define ATTN_SMEM ((128 + 2 * 128) * AST * 4)

__global__ __launch_bounds__(128) void attn_kernel()
{
    extern __shared__ uint32_t sm[];
    uint32_t* Ps = sm;                    // [128][68]
    uint32_t* KV = Ps + 128 * AST;        // 2 stages x 128 rows x 68

    const int bh = blockIdx.y;
    const int q0 = blockIdx.x * 128;
    const int tid = threadIdx.x, wid = tid >> 5, lane = tid & 31;
    const int gr = lane >> 2, tig = lane & 3;
    const int warp_q = wid * 32;

    const uint32_t* qg = g_qb + (size_t)bh * T_LEN * HDIM;
    const uint32_t* kg = g_kb + (size_t)bh * T_LEN * HDIM;
    const uint32_t* vg = g_vb + (size_t)bh * T_LEN * HDIM;  // [d][t]

    // Prologue: stage Q tile into KV stage-0, ldsm into registers
    {
        #pragma unroll
        for (int j = 0; j < 16; j++) {
            int id = tid + 128 * j;
            int r = id >> 4, c4 = (id & 15) * 4;
            cpasync16(s2u(KV + r * AST + c4), qg + (size_t)(q0 + r) * HDIM + c4);
        }
        CP_COMMIT();
        asm volatile("cp.async.wait_group 0;");
        __syncthreads();
    }
    uint32_t qf[2][8][4];
    {
        const uint32_t q_base = s2u(KV);
        #pragma unroll
        for (int mi = 0; mi < 2; mi++)
            #pragma unroll
            for (int ks = 0; ks < 8; ks++) {
                int row = warp_q + mi * 16 + (lane & 15);
                int col = ks * 8 + 4 * (lane >> 4);
                ldsm4(qf[mi][ks][0], qf[mi][ks][1], qf[mi][ks][2], qf[mi][ks][3],
                      q_base + (row * AST + col) * 4);
            }
    }
    __syncthreads();   // Q region free -> KV stage 0

    // Preload K/V tile 0 into stage 0
    #pragma unroll
    for (int j = 0; j < 8; j++) {
        int id = tid + 128 * j;
        int row = id >> 4, c4 = (id & 15) * 4;
        cpasync16(s2u(KV + row * AST + c4), kg + (size_t)row * HDIM + c4);
        cpasync16(s2u(KV + (64 + row) * AST + c4), vg + (size_t)row * T_LEN + c4);
    }
    CP_COMMIT();

    float accO[2][8][4];
    #pragma unroll
    for (int mi = 0; mi < 2; mi++)
        #pragma unroll
        for (int nf = 0; nf < 8; nf++)
            #pragma unroll
            for (int r = 0; r < 4; r++) accO[mi][nf][r] = 0.f;
    float m_s[2][2] = {{-1e30f, -1e30f}, {-1e30f, -1e30f}};
    float l_s[2][2] = {{0.f, 0.f}, {0.f, 0.f}};

    const uint32_t ps_base = s2u(Ps);

    #pragma unroll 1
    for (int it = 0; it < T_LEN / 64; it++) {
        int cur = it & 1;
        if (it < T_LEN / 64 - 1) {
            int s0 = (it + 1) * 64;
            uint32_t* Kn = KV + (1 - cur) * 128 * AST;
            #pragma unroll
            for (int j = 0; j < 8; j++) {
                int id = tid + 128 * j;
                int row = id >> 4, c4 = (id & 15) * 4;
                cpasync16(s2u(Kn + row * AST + c4), kg + (size_t)(s0 + row) * HDIM + c4);
                cpasync16(s2u(Kn + (64 + row) * AST + c4),
                          vg + (size_t)row * T_LEN + s0 + c4);
            }
            CP_COMMIT();
            asm volatile("cp.async.wait_group 1;");
        } else {
            asm volatile("cp.async.wait_group 0;");
        }
        __syncthreads();

        const uint32_t ks_base = s2u(KV + cur * 128 * AST);
        const uint32_t vs_base = ks_base + 64 * AST * 4;

        // S = Q K^T (Q from registers)
        float sfr[2][8][4];
        #pragma unroll
        for (int mi = 0; mi < 2; mi++)
            #pragma unroll
            for (int nf = 0; nf < 8; nf++)
                #pragma unroll
                for (int r = 0; r < 4; r++) sfr[mi][nf][r] = 0.f;

        #pragma unroll
        for (int ks = 0; ks < 8; ks++) {
            int k8 = ks * 8;
            uint32_t kb[8][2];
            #pragma unroll
            for (int p = 0; p < 4; p++) {
                int row = 16 * p + (lane & 7) + ((lane >> 4) << 3);
                int col = k8 + 4 * ((lane >> 3) & 1);
                ldsm4(kb[2 * p][0], kb[2 * p][1], kb[2 * p + 1][0], kb[2 * p + 1][1],
                      ks_base + (row * AST + col) * 4);
            }
            #pragma unroll
            for (int mi = 0; mi < 2; mi++)
                #pragma unroll
                for (int nf = 0; nf < 8; nf++) mma8(sfr[mi][nf], qf[mi][ks], kb[nf]);
        }

        // Online softmax (base-2)
        #pragma unroll
        for (int mi = 0; mi < 2; mi++)
            #pragma unroll
            for (int rr = 0; rr < 2; rr++) {
                float mx = -1e30f;
                #pragma unroll
                for (int nf = 0; nf < 8; nf++)
                    mx = fmaxf(mx, fmaxf(sfr[mi][nf][rr * 2], sfr[mi][nf][rr * 2 + 1]));
                mx = fmaxf(mx, __shfl_xor_sync(0xffffffffu, mx, 1));
                mx = fmaxf(mx, __shfl_xor_sync(0xffffffffu, mx, 2));
                float mn = fmaxf(m_s[mi][rr], mx);
                float al = ex2f(m_s[mi][rr] - mn);
                m_s[mi][rr] = mn;
                float rs = 0.f;
                #pragma unroll
                for (int nf = 0; nf < 8; nf++) {
                    float p0 = ex2f(sfr[mi][nf][rr * 2] - mn);
                    float p1 = ex2f(sfr[mi][nf][rr * 2 + 1] - mn);
                    sfr[mi][nf][rr * 2] = p0;
                    sfr[mi][nf][rr * 2 + 1] = p1;
                    rs += p0 + p1;
                    accO[mi][nf][rr * 2] *= al;
                    accO[mi][nf][rr * 2 + 1] *= al;
                }
                rs += __shfl_xor_sync(0xffffffffu, rs, 1);
                rs += __shfl_xor_sync(0xffffffffu, rs, 2);
                l_s[mi][rr] = l_s[mi][rr] * al + rs;
            }

        // Store P (tf32) to warp-private Ps rows
        #pragma unroll
        for (int mi = 0; mi < 2; mi++)
            #pragma unroll
            for (int nf = 0; nf < 8; nf++) {
                int col = nf * 8 + 2 * tig;
                int rw = warp_q + mi * 16 + gr;
                *(uint2*)(Ps + rw * AST + col) =
                    make_uint2(f2tf(sfr[mi][nf][0]), f2tf(sfr[mi][nf][1]));
                *(uint2*)(Ps + (rw + 8) * AST + col) =
                    make_uint2(f2tf(sfr[mi][nf][2]), f2tf(sfr[mi][nf][3]));
            }
        __syncwarp();

        // O += P V
        #pragma unroll
        for (int ks = 0; ks < 8; ks++) {
            int s8 = ks * 8;
            uint32_t vb[8][2];
            #pragma unroll
            for (int p = 0; p < 4; p++) {
                int row = 16 * p + (lane & 7) + ((lane >> 4) << 3);
                int col = s8 + 4 * ((lane >> 3) & 1);
                ldsm4(vb[2 * p][0], vb[2 * p][1], vb[2 * p + 1][0], vb[2 * p + 1][1],
                      vs_base + (row * AST + col) * 4);
            }
            #pragma unroll
            for (int mi = 0; mi < 2; mi++) {
                uint32_t a[4];
                int row = warp_q + mi * 16 + (lane & 15);
                int col = s8 + 4 * (lane >> 4);
                ldsm4(a[0], a[1], a[2], a[3], ps_base + (row * AST + col) * 4);
                #pragma unroll
                for (int nf = 0; nf < 8; nf++) mma8(accO[mi][nf], a, vb[nf]);
            }
        }
        __syncthreads();
    }

    // Normalize and write ctx[t*2+b][h*64+d]
    const int bb = bh >> 4;
    const int h = bh & 15;
    #pragma unroll
    for (int mi = 0; mi < 2; mi++)
        #pragma unroll
        for (int rr = 0; rr < 2; rr++) {
            float inv = 1.0f / l_s[mi][rr];
            int t = q0 + warp_q + mi * 16 + gr + 8 * rr;
            #pragma unroll
            for (int nf = 0; nf < 8; nf++) {
                int d = nf * 8 + 2 * tig;
                *(float2*)(g_ctx + ((size_t)t * BATCH + bb) * EMBED + h * HDIM + d) =
                    make_float2(accO[mi][nf][rr * 2] * inv,
                                accO[mi][nf][rr * 2 + 1] * inv);
            }
        }
}

// ---------------------------------------------------------------------------
// Kernel 3: output projection (tf32 tensor core).  Same core as kernel 1.
// ---------------------------------------------------------------------------
__global__ __launch_bounds__(256) void outproj_kernel(
    const float* __restrict__ w,      // [1024,1024]
    const float* __restrict__ bias,   // [1024]
    float* __restrict__ out)          // [4096,1024]
{
    __shared__ __align__(16) uint32_t As[128 * GST];
    __shared__ __align__(16) uint32_t Bs[128 * GST];

    const int bm = blockIdx.y * 128, bn = blockIdx.x * 128;
    const int tid = threadIdx.x, wid = tid >> 5, lane = tid & 31;
    const int gr = lane >> 2, tig = lane & 3;
    const int wm = (wid & 1) * 64, wn = (wid >> 1) * 32;
    const int r0 = tid >> 3, q = tid & 7;

    float acc[4][4][4];
    #pragma unroll
    for (int i = 0; i < 4; i++)
        #pragma unroll
        for (int j = 0; j < 4; j++)
            #pragma unroll
            for (int r = 0; r < 4; r++) acc[i][j][r] = 0.f;

    const float* ap = g_ctx + (size_t)(bm + r0) * EMBED + q * 4;
    const float* bp = w + (size_t)(bn + r0) * EMBED + q * 4;

    float4 pa[4], pb[4];
    #pragma unroll
    for (int it = 0; it < 4; it++) {
        pa[it] = *(const float4*)(ap + (size_t)it * 32 * EMBED);
        pb[it] = *(const float4*)(bp + (size_t)it * 32 * EMBED);
    }
    #pragma unroll
    for (int it = 0; it < 4; it++) {
        *(uint4*)(As + (r0 + 32 * it) * GST + q * 4) =
            make_uint4(f2tf(pa[it].x), f2tf(pa[it].y), f2tf(pa[it].z), f2tf(pa[it].w));
        *(uint4*)(Bs + (r0 + 32 * it) * GST + q * 4) =
            make_uint4(f2tf(pb[it].x), f2tf(pb[it].y), f2tf(pb[it].z), f2tf(pb[it].w));
    }
    __syncthreads();

    const uint32_t as_base = s2u(As), bs_base = s2u(Bs);

    #pragma unroll 1
    for (int kb = 0; kb < 32; kb++) {
        if (kb < 31) {
            int k0 = (kb + 1) * 32;
            #pragma unroll
            for (int it = 0; it < 4; it++) {
                pa[it] = *(const float4*)(ap + (size_t)it * 32 * EMBED + k0);
                pb[it] = *(const float4*)(bp + (size_t)it * 32 * EMBED + k0);
            }
        }
        #pragma unroll
        for (int ks = 0; ks < 4; ks++) {
            int k8 = ks * 8;
            uint32_t bfr[4][2];
            #pragma unroll
            for (int p = 0; p < 2; p++) {
                int row = wn + 16 * p + (lane & 7) + ((lane >> 4) << 3);
                int col = k8 + 4 * ((lane >> 3) & 1);
                ldsm4(bfr[2 * p][0], bfr[2 * p][1], bfr[2 * p + 1][0], bfr[2 * p + 1][1],
                      bs_base + (row * GST + col) * 4);
            }
            #pragma unroll
            for (int mi = 0; mi < 4; mi++) {
                uint32_t a[4];
                int row = wm + 16 * mi + (lane & 15);
                int col = k8 + 4 * (lane >> 4);
                ldsm4(a[0], a[1], a[2], a[3], as_base + (row * GST + col) * 4);
                #pragma unroll
                for (int nj = 0; nj < 4; nj++) mma8(acc[mi][nj], a, bfr[nj]);
            }
        }
        __syncthreads();
        if (kb < 31) {
            #pragma unroll
            for (int it = 0; it < 4; it++) {
                *(uint4*)(As + (r0 + 32 * it) * GST + q * 4) =
                    make_uint4(f2tf(pa[it].x), f2tf(pa[it].y), f2tf(pa[it].z), f2tf(pa[it].w));
                *(uint4*)(Bs + (r0 + 32 * it) * GST + q * 4) =
                    make_uint4(f2tf(pb[it].x), f2tf(pb[it].y), f2tf(pb[it].z), f2tf(pb[it].w));
            }
            __syncthreads();
        }
    }

    #pragma unroll
    for (int mi = 0; mi < 4; mi++)
        #pragma unroll
        for (int nj = 0; nj < 4; nj++)
            #pragma unroll
            for (int rr = 0; rr < 2; rr++) {
                int m = bm + wm + mi * 16 + gr + 8 * rr;
                int f = bn + wn + nj * 8 + 2 * tig;
                *(float2*)(out + (size_t)m * EMBED + f) =
                    make_float2(acc[mi][nj][rr * 2 + 0] + bias[f],
                                acc[mi][nj][rr * 2 + 1] + bias[f + 1]);
            }
}

// ---------------------------------------------------------------------------
extern "C" void kernel_launch(void* const* d_in, const int* in_sizes, int n_in,
                              void* d_out, int out_size)
{
    const float* x  = (const float*)d_in[0];   // [2048,2,1024]
    const float* w1 = (const float*)d_in[1];   // [3072,1024]
    const float* b1 = (const float*)d_in[2];   // [3072]
    const float* w2 = (const float*)d_in[3];   // [1024,1024]
    const float* b2 = (const float*)d_in[4];   // [1024]
    float* out = (float*)d_out;

    static bool attr_set = false;
    if (!attr_set) {
        cudaFuncSetAttribute(attn_kernel,
                             cudaFuncAttributeMaxDynamicSharedMemorySize, ATTN_SMEM);
        attr_set = true;
    }

    qkv_kernel<<<dim3(24, 32), 256>>>(x, w1, b1);
    vtrans_kernel<<<dim3(T_LEN / 64, BHEAD), 256>>>();
    attn_kernel<<<dim3(T_LEN / 128, BHEAD), 128, ATTN_SMEM>>>();
    outproj_kernel<<<dim3(8, 32), 256>>>(w2, b2, out);
}